// round 1
// baseline (speedup 1.0000x reference)
#include <cuda_runtime.h>
#include <mma.h>
using namespace nvcuda;

// Problem shape (fixed)
static constexpr int Bb = 2, Tt = 2048, Cc = 1024, Hh = 16, Dd = 64;

// Scratch (allocation-free: device globals)
__device__ float g_qkv[(size_t)Bb * Tt * 3 * Cc];          // 50 MB
__device__ float g_scores[(size_t)Bb * Hh * Tt * Tt];      // 512 MB
__device__ float g_y[(size_t)Bb * Tt * Cc];                // 16 MB

// ---------------------------------------------------------------------------
// Generic tf32 wmma GEMM: C = alpha * A @ op(B)
//   A: [M,K] row-major (lda)
//   B_KN=false: B stored [N,K] row-major (i.e. compute A @ B^T)   -> col_major frag
//   B_KN=true : B stored [K,N] row-major (i.e. compute A @ B)     -> row_major frag
// Batched via blockIdx.z: z -> (zb = z/Hh, zh = z%Hh), per-matrix strides.
// All of M, N multiples of 64; K multiple of 16 (true for every call here).
// ---------------------------------------------------------------------------
static constexpr int BM = 64, BN = 64, BK = 16;

template <bool B_KN>
__global__ void __launch_bounds__(128)
gemm_tf32(const float* __restrict__ A, int lda, long a_sh, long a_sb,
          const float* __restrict__ Bm, int ldb, long b_sh, long b_sb,
          float* __restrict__ Cm, int ldc, long c_sh, long c_sb,
          int K, float alpha)
{
    const int z = blockIdx.z;
    const long zb = z / Hh, zh = z % Hh;
    A  += zb * a_sb + zh * a_sh;
    Bm += zb * b_sb + zh * b_sh;
    Cm += zb * c_sb + zh * c_sh;

    const int bm = blockIdx.y * BM;
    const int bn = blockIdx.x * BN;

    const int tid  = threadIdx.x;
    const int warp = tid >> 5;
    const int wm   = (warp >> 1) * 32;   // warp grid 2x2, warp tile 32x32
    const int wn   = (warp & 1) * 32;

    constexpr int LDA_S = BK + 4;                        // 20 floats (80B, 16B-mult)
    constexpr int LDB_S = B_KN ? (BN + 4) : (BK + 4);    // 68 or 20
    __shared__ float As[BM * LDA_S];
    __shared__ float Bs[B_KN ? (BK * (BN + 4)) : (BN * (BK + 4))];

    wmma::fragment<wmma::accumulator, 16, 16, 8, float> acc[2][2];
#pragma unroll
    for (int i = 0; i < 2; i++)
#pragma unroll
        for (int j = 0; j < 2; j++)
            wmma::fill_fragment(acc[i][j], 0.0f);

    for (int k0 = 0; k0 < K; k0 += BK) {
        __syncthreads();
        // A tile: 64x16
#pragma unroll
        for (int i = tid; i < BM * BK; i += 128) {
            int r = i >> 4, c = i & 15;
            As[r * LDA_S + c] = A[(long)(bm + r) * lda + (k0 + c)];
        }
        if (B_KN) {
            // B tile: [BK][BN] rows of B[K,N]
#pragma unroll
            for (int i = tid; i < BK * BN; i += 128) {
                int r = i >> 6, c = i & 63;
                Bs[r * LDB_S + c] = Bm[(long)(k0 + r) * ldb + (bn + c)];
            }
        } else {
            // B tile: [BN][BK] rows of B[N,K]
#pragma unroll
            for (int i = tid; i < BN * BK; i += 128) {
                int r = i >> 4, c = i & 15;
                Bs[r * LDB_S + c] = Bm[(long)(bn + r) * ldb + (k0 + c)];
            }
        }
        __syncthreads();

#pragma unroll
        for (int ks = 0; ks < BK; ks += 8) {
            wmma::fragment<wmma::matrix_a, 16, 16, 8, wmma::precision::tf32,
                           wmma::row_major> af[2];
#pragma unroll
            for (int i = 0; i < 2; i++) {
                wmma::load_matrix_sync(af[i], &As[(wm + 16 * i) * LDA_S + ks], LDA_S);
#pragma unroll
                for (int t = 0; t < af[i].num_elements; t++)
                    af[i].x[t] = wmma::__float_to_tf32(af[i].x[t]);
            }
            if (B_KN) {
                wmma::fragment<wmma::matrix_b, 16, 16, 8, wmma::precision::tf32,
                               wmma::row_major> bf[2];
#pragma unroll
                for (int j = 0; j < 2; j++) {
                    wmma::load_matrix_sync(bf[j], &Bs[ks * LDB_S + wn + 16 * j], LDB_S);
#pragma unroll
                    for (int t = 0; t < bf[j].num_elements; t++)
                        bf[j].x[t] = wmma::__float_to_tf32(bf[j].x[t]);
                }
#pragma unroll
                for (int i = 0; i < 2; i++)
#pragma unroll
                    for (int j = 0; j < 2; j++)
                        wmma::mma_sync(acc[i][j], af[i], bf[j], acc[i][j]);
            } else {
                wmma::fragment<wmma::matrix_b, 16, 16, 8, wmma::precision::tf32,
                               wmma::col_major> bf[2];
#pragma unroll
                for (int j = 0; j < 2; j++) {
                    wmma::load_matrix_sync(bf[j], &Bs[(wn + 16 * j) * LDB_S + ks], LDB_S);
#pragma unroll
                    for (int t = 0; t < bf[j].num_elements; t++)
                        bf[j].x[t] = wmma::__float_to_tf32(bf[j].x[t]);
                }
#pragma unroll
                for (int i = 0; i < 2; i++)
#pragma unroll
                    for (int j = 0; j < 2; j++)
                        wmma::mma_sync(acc[i][j], af[i], bf[j], acc[i][j]);
            }
        }
    }

#pragma unroll
    for (int i = 0; i < 2; i++)
#pragma unroll
        for (int j = 0; j < 2; j++) {
#pragma unroll
            for (int t = 0; t < acc[i][j].num_elements; t++)
                acc[i][j].x[t] *= alpha;
            wmma::store_matrix_sync(
                Cm + (long)(bm + wm + 16 * i) * ldc + (bn + wn + 16 * j),
                acc[i][j], ldc, wmma::mem_row_major);
        }
}

// ---------------------------------------------------------------------------
// Row softmax over rows of length Tt=2048. One block (256 thr) per row,
// 8 elements/thread held in registers: one gmem read + one write.
// ---------------------------------------------------------------------------
__global__ void __launch_bounds__(256) softmax_rows(float* __restrict__ S)
{
    __shared__ float red[8];
    const long row = blockIdx.x;
    float* p = S + row * (long)Tt;
    const int tid = threadIdx.x;

    float4 a = ((float4*)p)[tid];
    float4 b = ((float4*)p)[tid + 256];

    float m = fmaxf(fmaxf(fmaxf(a.x, a.y), fmaxf(a.z, a.w)),
                    fmaxf(fmaxf(b.x, b.y), fmaxf(b.z, b.w)));
#pragma unroll
    for (int o = 16; o; o >>= 1) m = fmaxf(m, __shfl_xor_sync(0xffffffffu, m, o));
    if ((tid & 31) == 0) red[tid >> 5] = m;
    __syncthreads();
    m = red[0];
#pragma unroll
    for (int i = 1; i < 8; i++) m = fmaxf(m, red[i]);
    __syncthreads();

    a.x = __expf(a.x - m); a.y = __expf(a.y - m);
    a.z = __expf(a.z - m); a.w = __expf(a.w - m);
    b.x = __expf(b.x - m); b.y = __expf(b.y - m);
    b.z = __expf(b.z - m); b.w = __expf(b.w - m);

    float s = (a.x + a.y + a.z + a.w) + (b.x + b.y + b.z + b.w);
#pragma unroll
    for (int o = 16; o; o >>= 1) s += __shfl_xor_sync(0xffffffffu, s, o);
    if ((tid & 31) == 0) red[tid >> 5] = s;
    __syncthreads();
    s = red[0];
#pragma unroll
    for (int i = 1; i < 8; i++) s += red[i];

    const float inv = 1.0f / s;
    a.x *= inv; a.y *= inv; a.z *= inv; a.w *= inv;
    b.x *= inv; b.y *= inv; b.z *= inv; b.w *= inv;
    ((float4*)p)[tid]       = a;
    ((float4*)p)[tid + 256] = b;
}

// ---------------------------------------------------------------------------
extern "C" void kernel_launch(void* const* d_in, const int* in_sizes, int n_in,
                              void* d_out, int out_size)
{
    const float* x     = (const float*)d_in[0];
    const float* W_qkv = (const float*)d_in[3];
    const float* W_out = (const float*)d_in[4];
    float* out = (float*)d_out;

    float *qkv, *scores, *y;
    cudaGetSymbolAddress((void**)&qkv, g_qkv);
    cudaGetSymbolAddress((void**)&scores, g_scores);
    cudaGetSymbolAddress((void**)&y, g_y);

    const long sQKV_b = (long)Tt * 3 * Cc;   // per-batch stride in qkv
    const long sS_h   = (long)Tt * Tt;       // per-head stride in scores
    const long sS_b   = (long)Hh * Tt * Tt;

    // 1) qkv = x @ W_qkv^T : [4096,3072,1024]
    gemm_tf32<false><<<dim3(3 * Cc / BN, Bb * Tt / BM, 1), 128>>>(
        x, Cc, 0, 0,
        W_qkv, Cc, 0, 0,
        qkv, 3 * Cc, 0, 0,
        Cc, 1.0f);

    // 2) scores[b,h] = Q[b,h] @ K[b,h]^T / 8 : 32 x [2048,2048,64]
    gemm_tf32<false><<<dim3(Tt / BN, Tt / BM, Bb * Hh), 128>>>(
        qkv, 3 * Cc, Dd, sQKV_b,              // Q slice
        qkv + Cc, 3 * Cc, Dd, sQKV_b,         // K slice
        scores, Tt, sS_h, sS_b,
        Dd, 0.125f);

    // 3) softmax over the last dim
    softmax_rows<<<Bb * Hh * Tt, 256>>>(scores);

    // 4) y[b,h] = P[b,h] @ V[b,h] : 32 x [2048,64,2048], B is [K,N]
    gemm_tf32<true><<<dim3(Dd / BN, Tt / BM, Bb * Hh), 128>>>(
        scores, Tt, sS_h, sS_b,
        qkv + 2 * Cc, 3 * Cc, Dd, sQKV_b,     // V slice
        y, Cc, Dd, (long)Tt * Cc,
        Tt, 1.0f);

    // 5) out = y @ W_out^T : [4096,1024,1024]
    gemm_tf32<false><<<dim3(Cc / BN, Bb * Tt / BM, 1), 128>>>(
        y, Cc, 0, 0,
        W_out, Cc, 0, 0,
        out, Cc, 0, 0,
        Cc, 1.0f);
}